// round 9
// baseline (speedup 1.0000x reference)
#include <cuda_runtime.h>

#define NEG_PENALTY 0.03f
#define BATCH 64
#define NCLS  2048
#define LL    1024
#define NT    1024
#define GRID  BATCH
#define FULLM 0xffffffffu
#define POS_PAD 8.0f                  // > any x+PEN  -> max(x,8)-8 == 0 exactly
#define NEG_PAD -1e30f                // max(NEG_PAD+PEN,p)-p == 0 exactly

__device__ float    g_partial[GRID];
__device__ unsigned g_ticket = 0;     // self-resetting via atomicInc wrap

__global__ __launch_bounds__(NT)
void ranking_loss_kernel(const float* __restrict__ ranks,
                         const int*   __restrict__ labels,
                         const void*  __restrict__ ids_raw,
                         float* __restrict__ out)
{
    __shared__ __align__(16) float s_pos[LL + 8];
    __shared__ __align__(16) float s_neg[LL + 8];
    __shared__ int   s_pcnt[32];      // pos count per 32-elem round
    __shared__ int   s_pexc[32];      // exclusive prefix of counts
    __shared__ float s_warp[32];
    __shared__ int   s_np;

    const int b    = blockIdx.x;      // one CTA per batch
    const int tid  = threadIdx.x;
    const int lane = tid & 31;
    const int wid  = tid >> 5;        // 0..31

    // --- dtype sniff: int64 ids have zero high words at odd 32-bit indices ---
    const int* w32 = (const int*)ids_raw;
    const bool is64 = ((w32[201] | w32[401] | w32[601] | w32[801]) == 0);
    const long long* w64 = (const long long*)ids_raw;

    // ---- gather (1 elem/thread; id coalesced, rank/label scattered indep) ----
    int id = is64 ? (int)w64[tid] : w32[tid];
    const float* rrow = ranks  + b * NCLS;
    const int*   lrow = labels + b * NCLS;
    float r = __ldg(&rrow[id]);
    int   l = __ldg(&lrow[id]);

    // ---- deterministic index-ordered partition ----
    const bool ispos = (l == 1);
    const unsigned m = __ballot_sync(FULLM, ispos);
    if (lane == 0) s_pcnt[wid] = __popc(m);
    __syncthreads();                                   // BAR 1
    if (wid == 0) {                    // exclusive scan of 32 round counts
        int c = s_pcnt[lane];
        int inc = c;
        #pragma unroll
        for (int d = 1; d < 32; d <<= 1) {
            int t = __shfl_up_sync(FULLM, inc, d);
            if (lane >= d) inc += t;
        }
        s_pexc[lane] = inc - c;
        if (lane == 31) s_np = inc;
    }
    __syncthreads();                                   // BAR 2

    const int np = s_np;
    const int nn = LL - np;
    {
        int rlt = __popc(m & ((1u << lane) - 1u));
        int bp  = s_pexc[wid];
        int bn  = wid * 32 - bp;
        if (ispos) s_pos[bp + rlt]          = r;
        else       s_neg[bn + (lane - rlt)] = r;
    }
    // pads (written after indices known; barrier below orders vs readers)
    const int np4    = (np + 3) & ~3;
    const int count4 = (nn + 3) & ~3;
    if (tid < np4 - np)    s_pos[np + tid] = POS_PAD;
    if (tid < count4 - nn) s_neg[nn + tid] = NEG_PAD;
    __syncthreads();                                   // BAR 3

    // ---- dense pair eval: acc = sum(max(x',p)) - 4*sum(p) over own tile ----
    // 1024 threads = 128 neg-groups (4 negs) x 8 pos-chunks.
    // pq is warp-uniform -> pos LDS.128 is a pure 32-lane broadcast.
    const int jt = tid & 127;
    const int pq = tid >> 7;              // 0..7
    const int g  = np4 >> 2;              // # float4 pos groups
    const int cg = (g + 7) >> 3;          // groups per chunk
    const int g0 = min(pq * cg, g);
    const int g1 = min(g0 + cg, g);
    const float4* pos4 = (const float4*)s_pos;

    float acc = 0.0f;
    for (int j = (jt << 2); j < count4; j += 512) {
        float4 xq = *(const float4*)(s_neg + j);
        float x0 = xq.x + NEG_PENALTY;
        float x1 = xq.y + NEG_PENALTY;
        float x2 = xq.z + NEG_PENALTY;
        float x3 = xq.w + NEG_PENALTY;
        float a0 = 0.0f, a1 = 0.0f, a2 = 0.0f, a3 = 0.0f, ps = 0.0f;
        for (int gi = g0; gi < g1; gi++) {
            float4 q = pos4[gi];
            a0 += fmaxf(x0, q.x); a1 += fmaxf(x1, q.x);
            a2 += fmaxf(x2, q.x); a3 += fmaxf(x3, q.x);
            a0 += fmaxf(x0, q.y); a1 += fmaxf(x1, q.y);
            a2 += fmaxf(x2, q.y); a3 += fmaxf(x3, q.y);
            a0 += fmaxf(x0, q.z); a1 += fmaxf(x1, q.z);
            a2 += fmaxf(x2, q.z); a3 += fmaxf(x3, q.z);
            a0 += fmaxf(x0, q.w); a1 += fmaxf(x1, q.w);
            a2 += fmaxf(x2, q.w); a3 += fmaxf(x3, q.w);
            ps += (q.x + q.y) + (q.z + q.w);
        }
        acc += ((a0 + a1) + (a2 + a3)) - 4.0f * ps;
    }

    // ---- block reduce (32 warps) ----
    #pragma unroll
    for (int d = 16; d >= 1; d >>= 1)
        acc += __shfl_down_sync(FULLM, acc, d);
    if (lane == 0) s_warp[wid] = acc;
    __syncthreads();                                   // BAR 4
    if (wid == 0) {
        float a2r = s_warp[lane];
        #pragma unroll
        for (int d = 16; d >= 1; d >>= 1)
            a2r += __shfl_down_sync(FULLM, a2r, d);
        int is_last = 0;
        if (lane == 0) {
            g_partial[b] = a2r;
            __threadfence();
            unsigned t = atomicInc(&g_ticket, GRID - 1);   // wraps at 63
            is_last = (t == GRID - 1);
        }
        is_last = __shfl_sync(FULLM, is_last, 0);
        // last CTA reduces the 64 partials in fixed order (deterministic)
        if (is_last) {
            volatile float* gp = g_partial;
            float v = gp[lane] + gp[lane + 32];
            #pragma unroll
            for (int d = 16; d >= 1; d >>= 1)
                v += __shfl_down_sync(FULLM, v, d);
            if (lane == 0) out[0] = v * (1.0f / (float)BATCH);
        }
    }
}

extern "C" void kernel_launch(void* const* d_in, const int* in_sizes, int n_in,
                              void* d_out, int out_size)
{
    const float* ranks  = (const float*)d_in[0];   // [B, C] f32
    const int*   labels = (const int*)d_in[1];     // [B, C] i32
    const void*  ids    = d_in[2];                 // [L] i64 or i32 (sniffed)
    float* out = (float*)d_out;                    // [1] f32

    ranking_loss_kernel<<<GRID, NT>>>(ranks, labels, ids, out);
}

// round 10
// speedup vs baseline: 1.4659x; 1.4659x over previous
#include <cuda_runtime.h>

#define NEG_PENALTY 0.03f
#define BATCH 64
#define NCLS  2048
#define LL    1024
#define NT    1024
#define GRID  BATCH
#define NB    1024
#define FULLM 0xffffffffu
#define BMIN   (-6.5f)
#define BSCALE (1024.0f / 13.0f)   // buckets cover [-6.5, 6.5]; clamp handles tails

__device__ float    g_partial[GRID];
__device__ unsigned g_ticket = 0;   // self-resetting via atomicInc wrap

__device__ __forceinline__ int bucket_of(float v) {
    int bkt = (int)((v - BMIN) * BSCALE);
    return min(max(bkt, 0), NB - 1);
}

__global__ __launch_bounds__(NT)
void ranking_loss_kernel(const float* __restrict__ ranks,
                         const int*   __restrict__ labels,
                         const void*  __restrict__ ids_raw,
                         float* __restrict__ out)
{
    __shared__ int   s_bcnt[NB];       // per-bucket pos count
    __shared__ int   s_boff[NB + 1];   // exclusive offsets (counting sort)
    __shared__ float s_sorted[LL];     // value-sorted pos (zeros beyond np)
    __shared__ float s_pre[LL];        // inclusive prefix sums of s_sorted
    __shared__ int   s_iscan[32];
    __shared__ float s_fscan[32];
    __shared__ float s_warp[32];

    const int b    = blockIdx.x;       // one CTA per batch
    const int tid  = threadIdx.x;
    const int lane = tid & 31;
    const int wid  = tid >> 5;

    // --- dtype sniff: int64 ids have zero high words at odd 32-bit indices ---
    const int* w32 = (const int*)ids_raw;
    const bool is64 = ((w32[201] | w32[401] | w32[601] | w32[801]) == 0);
    const long long* w64 = (const long long*)ids_raw;

    // ---- gather (1 elem/thread) ----
    int id = is64 ? (int)w64[tid] : w32[tid];
    const float* rrow = ranks  + b * NCLS;
    const int*   lrow = labels + b * NCLS;
    float r = __ldg(&rrow[id]);
    int   l = __ldg(&lrow[id]);

    const bool  ispos = (l == 1);
    const float x     = r + NEG_PENALTY;          // only used if neg
    const int   bkt   = bucket_of(ispos ? r : x); // monotone map

    s_bcnt[tid]   = 0;
    s_sorted[tid] = 0.0f;
    __syncthreads();                                  // B0

    int sidx = 0;
    if (ispos) sidx = atomicAdd(&s_bcnt[bkt], 1);
    __syncthreads();                                  // B1

    // ---- block scan of bucket counts -> exclusive offsets ----
    int v = s_bcnt[tid];
    int inc = v;
    #pragma unroll
    for (int d = 1; d < 32; d <<= 1) {
        int t = __shfl_up_sync(FULLM, inc, d);
        if (lane >= d) inc += t;
    }
    if (lane == 31) s_iscan[wid] = inc;
    __syncthreads();                                  // B2
    if (wid == 0) {
        int wv = s_iscan[lane];
        int winc = wv;
        #pragma unroll
        for (int d = 1; d < 32; d <<= 1) {
            int t = __shfl_up_sync(FULLM, winc, d);
            if (lane >= d) winc += t;
        }
        s_iscan[lane] = winc;
    }
    __syncthreads();                                  // B3
    int excl = ((wid > 0) ? s_iscan[wid - 1] : 0) + inc - v;
    s_boff[tid] = excl;
    if (tid == NT - 1) s_boff[NB] = excl + v;         // = np
    __syncthreads();                                  // B4

    // ---- counting-sort scatter of pos values ----
    if (ispos) s_sorted[s_boff[bkt] + sidx] = r;
    __syncthreads();                                  // B5

    // ---- block scan of sorted values -> inclusive prefix sums ----
    float fv = s_sorted[tid];
    float finc = fv;
    #pragma unroll
    for (int d = 1; d < 32; d <<= 1) {
        float t = __shfl_up_sync(FULLM, finc, d);
        if (lane >= d) finc += t;
    }
    if (lane == 31) s_fscan[wid] = finc;
    __syncthreads();                                  // B6
    if (wid == 0) {
        float wv = s_fscan[lane];
        float winc = wv;
        #pragma unroll
        for (int d = 1; d < 32; d <<= 1) {
            float t = __shfl_up_sync(FULLM, winc, d);
            if (lane >= d) winc += t;
        }
        s_fscan[lane] = winc;
    }
    __syncthreads();                                  // B7
    s_pre[tid] = ((wid > 0) ? s_fscan[wid - 1] : 0.0f) + finc;
    __syncthreads();                                  // B8

    // ---- per-neg closed form: (k0+c)*x - (S0+s) ----
    float acc = 0.0f;
    if (!ispos) {
        int k0 = s_boff[bkt];          // pos strictly in lower buckets (< x)
        int e  = s_boff[bkt + 1];
        int c = 0; float s = 0.0f;
        for (int i = k0; i < e; i++) { // partial bucket, ~0-3 elems
            float p = s_sorted[i];
            if (p < x) { c++; s += p; }
        }
        float S0 = (k0 > 0) ? s_pre[k0 - 1] : 0.0f;
        acc = (float)(k0 + c) * x - (S0 + s);
    }

    // ---- block reduce (32 warps) + fused deterministic tail ----
    #pragma unroll
    for (int d = 16; d >= 1; d >>= 1)
        acc += __shfl_down_sync(FULLM, acc, d);
    if (lane == 0) s_warp[wid] = acc;
    __syncthreads();                                  // B9
    if (wid == 0) {
        float a2 = s_warp[lane];
        #pragma unroll
        for (int d = 16; d >= 1; d >>= 1)
            a2 += __shfl_down_sync(FULLM, a2, d);
        int is_last = 0;
        if (lane == 0) {
            g_partial[b] = a2;
            __threadfence();
            unsigned t = atomicInc(&g_ticket, GRID - 1);  // wraps at 63
            is_last = (t == GRID - 1);
        }
        is_last = __shfl_sync(FULLM, is_last, 0);
        if (is_last) {   // last CTA reduces partials in fixed order
            volatile float* gp = g_partial;
            float vv = gp[lane] + gp[lane + 32];
            #pragma unroll
            for (int d = 16; d >= 1; d >>= 1)
                vv += __shfl_down_sync(FULLM, vv, d);
            if (lane == 0) out[0] = vv * (1.0f / (float)BATCH);
        }
    }
}

extern "C" void kernel_launch(void* const* d_in, const int* in_sizes, int n_in,
                              void* d_out, int out_size)
{
    const float* ranks  = (const float*)d_in[0];   // [B, C] f32
    const int*   labels = (const int*)d_in[1];     // [B, C] i32
    const void*  ids    = d_in[2];                 // [L] i64 or i32 (sniffed)
    float* out = (float*)d_out;                    // [1] f32

    ranking_loss_kernel<<<GRID, NT>>>(ranks, labels, ids, out);
}